// round 14
// baseline (speedup 1.0000x reference)
#include <cuda_runtime.h>
#include <math.h>

#define BB  32
#define PP  24
#define HHN 24
#define EE  300
#define DD  512
#define GG  4096   // 8*D
#define DR  25     // slot 0 = zero boundary, slots 1..24 = grid rows 0..23
#define NB  148    // persistent blocks (<= SM count, 1 block/SM guaranteed)

// Split-K condense partials: g_ph[ks][slot][b][n] = partial (no bias) of
// h-state over k-range [ks*256,(ks+1)*256). Slot = absolute row i + 1.
// Slot 0 never written -> stays zero -> zero boundary. Consumers sum 4
// partials + bias.
__device__ float g_ph[4][DR][BB][DD];
__device__ float g_pc[4][DR][BB][DD];
__device__ float g_zb[DD];              // zero bias page (never written)
// Hoisted input projections
__device__ float g_A[PP][BB][GG];
__device__ float g_Bh[HHN][BB][GG];
// Per-diagonal LSTM cell outputs (pre-condense), indexed by cell-on-diagonal.
__device__ float g_h2[HHN][BB][2*DD];
__device__ float g_c2[HHN][BB][2*DD];
// MLP intermediates
__device__ float g_m1[BB][DD];
__device__ float g_m2[BB][DD];

// Grid barrier state (returns to {0,0} after every launch: 94 = even syncs
// -> sense ends at 0; counter wraps to 0 at each barrier; plus explicit reset).
__device__ unsigned g_bar_cnt;
__device__ volatile unsigned g_bar_flag;

__device__ __forceinline__ float sigf(float x) { return 1.0f / (1.0f + expf(-x)); }

// Packed dual-FMA (sm_100+): d.lo += a.lo*b.lo ; d.hi += a.hi*b.hi
#define FFMA2(d, a, b) asm("fma.rn.f32x2 %0, %1, %2, %0;" : "+l"(d) : "l"(a), "l"(b))

__device__ __forceinline__ float f2sum(unsigned long long v) {
    return __uint_as_float((unsigned)v) + __uint_as_float((unsigned)(v >> 32));
}

// Sense-reversing centralized grid barrier. All NB blocks co-resident.
__device__ __forceinline__ void gsync(unsigned &sense) {
    __syncthreads();
    if (threadIdx.x == 0) {
        sense ^= 1u;
        __threadfence();
        unsigned old = atomicInc(&g_bar_cnt, NB - 1);
        if (old == NB - 1) {
            g_bar_flag = sense;
        } else {
            while (g_bar_flag != sense) __nanosleep(64);
        }
        __threadfence();
    }
    __syncthreads();
}

// ---------------------------------------------------------------------------
// Prologue: gather embeddings + input GEMMs into g_A / g_Bh.
// grid = (24 seq, 32 n-chunks of 128, 2 [A|Bh]), block = 256
// ---------------------------------------------------------------------------
__global__ void __launch_bounds__(256) prologue_kernel(
    const int* __restrict__ premise, const int* __restrict__ hypothesis,
    const float* __restrict__ emb, const float* __restrict__ W_ih,
    const float* __restrict__ b_ih, const float* __restrict__ b_hh)
{
    int seq = blockIdx.x;
    int n0  = blockIdx.y * 128;
    bool isA = (blockIdx.z == 0);
    const int* sidx = isA ? premise : hypothesis;   // both [B,24] row-major
    int coff = isA ? 0 : EE;

    __shared__ float Xs[32][33];
    __shared__ float Ws[128][33];
    __shared__ int   rows[32];

    int tid = threadIdx.x;
    int tr = tid >> 5, tc = tid & 31;
    if (tid < 32) rows[tid] = sidx[tid * 24 + seq];
    __syncthreads();

    float acc[4][4];
#pragma unroll
    for (int a = 0; a < 4; a++)
#pragma unroll
        for (int b = 0; b < 4; b++) acc[a][b] = 0.f;

    for (int k0 = 0; k0 < 320; k0 += 32) {
        {
            int b = tid >> 3;
            int kq = (tid & 7) * 4;
            int k = k0 + kq;
            float4 v = make_float4(0.f, 0.f, 0.f, 0.f);
            if (k < EE) v = *(const float4*)(emb + (long)rows[b] * EE + k);
            Xs[b][kq] = v.x; Xs[b][kq + 1] = v.y; Xs[b][kq + 2] = v.z; Xs[b][kq + 3] = v.w;
        }
#pragma unroll
        for (int t = 0; t < 4; t++) {
            int idx = tid + t * 256;
            int n = idx >> 3;
            int kq = (idx & 7) * 4;
            int k = k0 + kq;
            float4 w = make_float4(0.f, 0.f, 0.f, 0.f);
            if (k < EE) w = *(const float4*)(W_ih + (long)(n0 + n) * (2 * EE) + coff + k);
            Ws[n][kq] = w.x; Ws[n][kq + 1] = w.y; Ws[n][kq + 2] = w.z; Ws[n][kq + 3] = w.w;
        }
        __syncthreads();
#pragma unroll
        for (int kk = 0; kk < 32; kk++) {
            float xv[4], wv[4];
#pragma unroll
            for (int rr = 0; rr < 4; rr++) xv[rr] = Xs[tr + 8 * rr][kk];
#pragma unroll
            for (int cc = 0; cc < 4; cc++) wv[cc] = Ws[cc * 32 + tc][kk];
#pragma unroll
            for (int rr = 0; rr < 4; rr++)
#pragma unroll
                for (int cc = 0; cc < 4; cc++)
                    acc[rr][cc] = fmaf(xv[rr], wv[cc], acc[rr][cc]);
        }
        __syncthreads();
    }

    float* dst = isA ? &g_A[seq][0][0] : &g_Bh[seq][0][0];
#pragma unroll
    for (int rr = 0; rr < 4; rr++) {
        int b = tr + 8 * rr;
#pragma unroll
        for (int cc = 0; cc < 4; cc++) {
            int n = n0 + cc * 32 + tc;
            float v = acc[rr][cc];
            if (isA) v += b_ih[n] + b_hh[n];
            dst[b * GG + n] = v;
        }
    }
}

// ---------------------------------------------------------------------------
// Shared-memory tile storage used by both wavefront phases.
// ---------------------------------------------------------------------------
struct TileSmem {
    float Xs[2][32][32];          // [buf][b][kk]
    float Ws2[2][8][128][4];      // [buf][kqi][n^kqi][4]
};

// ---------------------------------------------------------------------------
// Gates tile: recurrent GEMM + fused LSTM nonlinearity for one (cell, m-chunk).
// C[32 x 128], K = 1024. X reconstructed as sum of 4 split-K partials + bias.
// ---------------------------------------------------------------------------
__device__ __forceinline__ void gates_tile(
    TileSmem& S, const float* __restrict__ W_hh,
    const float* __restrict__ b_ch, const float* __restrict__ b_cc,
    int d, int i, int ci, int m0)
{
    int j = d - i;

    int lsl = i;                              // left  (i-1, j): slot i
    int msl = (j == 0) ? 0 : (i + 1);         // lower (i, j-1): slot i+1
    const float* hbL = (i == 0) ? g_zb : b_ch;
    const float* hbM = (j == 0) ? g_zb : b_ch;
    const float* cbL = (i == 0) ? g_zb : b_cc;
    const float* cbM = (j == 0) ? g_zb : b_cc;

    int tid = threadIdx.x;
    int w = tid >> 5, tc = tid & 31;

    int kqi_w = tid & 7;
    const float* wp0, *wp1, *wp2, *wp3;
    int wn0, wn1, wn2, wn3;
    {
        int n0_ = (tid >> 3);
#define WROW(nn) (W_hh + (long)(((nn) >> 5) * 1024 + m0 + ((nn) & 31)) * 1024 + kqi_w * 4)
        wp0 = WROW(n0_);       wn0 = n0_ ^ kqi_w;
        wp1 = WROW(n0_ + 32);  wn1 = (n0_ + 32) ^ kqi_w;
        wp2 = WROW(n0_ + 64);  wn2 = (n0_ + 64) ^ kqi_w;
        wp3 = WROW(n0_ + 96);  wn3 = (n0_ + 96) ^ kqi_w;
#undef WROW
    }

    int xrow = tid >> 3;
    int xkq = (tid & 7) * 4;
    const float* lp0 = &g_ph[0][lsl][xrow][xkq];
    const float* lp1 = &g_ph[1][lsl][xrow][xkq];
    const float* lp2 = &g_ph[2][lsl][xrow][xkq];
    const float* lp3 = &g_ph[3][lsl][xrow][xkq];
    const float* mp0 = &g_ph[0][msl][xrow][xkq];
    const float* mp1 = &g_ph[1][msl][xrow][xkq];
    const float* mp2 = &g_ph[2][msl][xrow][xkq];
    const float* mp3 = &g_ph[3][msl][xrow][xkq];

    unsigned long long acc[4][4];
#pragma unroll
    for (int q = 0; q < 4; q++)
#pragma unroll
        for (int c = 0; c < 4; c++) acc[q][c] = 0ull;

    float4 xp0, xp1, xp2, xp3, xbv;
    float4 wr0, wr1, wr2, wr3;

#define G_FETCH(k0_) do {                                                    \
        if ((k0_) < 512) {                                                   \
            xp0 = *(const float4*)(lp0 + (k0_));                             \
            xp1 = *(const float4*)(lp1 + (k0_));                             \
            xp2 = *(const float4*)(lp2 + (k0_));                             \
            xp3 = *(const float4*)(lp3 + (k0_));                             \
            xbv = *(const float4*)(hbL + xkq + (k0_));                       \
        } else {                                                             \
            int kr_ = (k0_) - 512;                                           \
            xp0 = *(const float4*)(mp0 + kr_);                               \
            xp1 = *(const float4*)(mp1 + kr_);                               \
            xp2 = *(const float4*)(mp2 + kr_);                               \
            xp3 = *(const float4*)(mp3 + kr_);                               \
            xbv = *(const float4*)(hbM + xkq + kr_);                         \
        }                                                                    \
        wr0 = *(const float4*)(wp0 + (k0_));                                 \
        wr1 = *(const float4*)(wp1 + (k0_));                                 \
        wr2 = *(const float4*)(wp2 + (k0_));                                 \
        wr3 = *(const float4*)(wp3 + (k0_));                                 \
    } while (0)

#define G_STORE(bi_) do {                                                    \
        float4 xs_;                                                          \
        xs_.x = xbv.x + xp0.x + xp1.x + xp2.x + xp3.x;                       \
        xs_.y = xbv.y + xp0.y + xp1.y + xp2.y + xp3.y;                       \
        xs_.z = xbv.z + xp0.z + xp1.z + xp2.z + xp3.z;                       \
        xs_.w = xbv.w + xp0.w + xp1.w + xp2.w + xp3.w;                       \
        *(float4*)&S.Xs[bi_][xrow][xkq] = xs_;                               \
        *(float4*)&S.Ws2[bi_][kqi_w][wn0][0] = wr0;                          \
        *(float4*)&S.Ws2[bi_][kqi_w][wn1][0] = wr1;                          \
        *(float4*)&S.Ws2[bi_][kqi_w][wn2][0] = wr2;                          \
        *(float4*)&S.Ws2[bi_][kqi_w][wn3][0] = wr3;                          \
    } while (0)

#define G_COMPUTE(bi_) do {                                                  \
        _Pragma("unroll")                                                    \
        for (int kqi = 0; kqi < 8; kqi++) {                                  \
            ulonglong2 xv0 = *(const ulonglong2*)&S.Xs[bi_][4 * w + 0][kqi * 4]; \
            ulonglong2 xv1 = *(const ulonglong2*)&S.Xs[bi_][4 * w + 1][kqi * 4]; \
            ulonglong2 xv2 = *(const ulonglong2*)&S.Xs[bi_][4 * w + 2][kqi * 4]; \
            ulonglong2 xv3 = *(const ulonglong2*)&S.Xs[bi_][4 * w + 3][kqi * 4]; \
            _Pragma("unroll")                                                \
            for (int c = 0; c < 4; c++) {                                    \
                ulonglong2 wv = *(const ulonglong2*)&S.Ws2[bi_][kqi][(tc + 32 * c) ^ kqi][0]; \
                FFMA2(acc[0][c], xv0.x, wv.x); FFMA2(acc[0][c], xv0.y, wv.y); \
                FFMA2(acc[1][c], xv1.x, wv.x); FFMA2(acc[1][c], xv1.y, wv.y); \
                FFMA2(acc[2][c], xv2.x, wv.x); FFMA2(acc[2][c], xv2.y, wv.y); \
                FFMA2(acc[3][c], xv3.x, wv.x); FFMA2(acc[3][c], xv3.y, wv.y); \
            }                                                                \
        }                                                                    \
    } while (0)

    G_FETCH(0);
    G_STORE(0);
    G_FETCH(32);
    __syncthreads();

    for (int t = 0; t < 32; t++) {
        if (t + 1 < 32) G_STORE((t + 1) & 1);
        if (t + 2 < 32) G_FETCH((t + 2) * 32);
        G_COMPUTE(t & 1);
        __syncthreads();
    }
#undef G_FETCH
#undef G_STORE
#undef G_COMPUTE

    int m = m0 + tc;
    const float* Ai = &g_A[i][0][0];
    const float* Bj = &g_Bh[j][0][0];
    float* h2o = &g_h2[ci][0][0];
    float* c2o = &g_c2[ci][0][0];

    const float *cq0, *cq1, *cq2, *cq3;
    float cbv;
    if (m < DD) {
        cq0 = &g_pc[0][lsl][0][m]; cq1 = &g_pc[1][lsl][0][m];
        cq2 = &g_pc[2][lsl][0][m]; cq3 = &g_pc[3][lsl][0][m];
        cbv = cbL[m];
    } else {
        int mr = m - DD;
        cq0 = &g_pc[0][msl][0][mr]; cq1 = &g_pc[1][msl][0][mr];
        cq2 = &g_pc[2][msl][0][mr]; cq3 = &g_pc[3][msl][0][mr];
        cbv = cbM[mr];
    }

#pragma unroll
    for (int q = 0; q < 4; q++) {
        int b = 4 * w + q;
        long ab = (long)b * GG + m;
        float gi = f2sum(acc[q][0]) + Ai[ab]        + Bj[ab];
        float gf = f2sum(acc[q][1]) + Ai[ab + 1024] + Bj[ab + 1024];
        float gg = f2sum(acc[q][2]) + Ai[ab + 2048] + Bj[ab + 2048];
        float go = f2sum(acc[q][3]) + Ai[ab + 3072] + Bj[ab + 3072];
        float cp = cbv + cq0[b * DD] + cq1[b * DD] + cq2[b * DD] + cq3[b * DD];
        float c2 = sigf(gf) * cp + sigf(gi) * tanhf(gg);
        float h2 = sigf(go) * tanhf(c2);
        c2o[b * (2 * DD) + m] = c2;
        h2o[b * (2 * DD) + m] = h2;
    }
}

// ---------------------------------------------------------------------------
// Condense tile, split-K(4): one (cell, which/chunk/ksplit) job.
// C[32 x 128], K = 256 (8 tiles). Writes bias-free partials g_ph/g_pc[ks][i+1].
// ---------------------------------------------------------------------------
__device__ __forceinline__ void cond_tile(
    TileSmem& S, const float* __restrict__ W_ch, const float* __restrict__ W_cc,
    int i, int ci, int yy)
{
    int which = yy >> 4;                    // 0 -> h path, 1 -> c path
    int n0 = ((yy >> 2) & 3) * 128;
    int ks = yy & 3;
    int koff = ks * 256;

    const float* X = which ? &g_c2[ci][0][0] : &g_h2[ci][0][0];
    const float* W = which ? W_cc : W_ch;
    float* out = which ? &g_pc[ks][i + 1][0][0] : &g_ph[ks][i + 1][0][0];

    int tid = threadIdx.x;
    int w = tid >> 5, tc = tid & 31;

    int kqi_w = tid & 7;
    const float* wp0, *wp1, *wp2, *wp3;
    int wn0, wn1, wn2, wn3;
    {
        int n_ = (tid >> 3);
        wp0 = W + (long)(n0 + n_) * 1024 + koff + kqi_w * 4;       wn0 = n_ ^ kqi_w;
        wp1 = W + (long)(n0 + n_ + 32) * 1024 + koff + kqi_w * 4;  wn1 = (n_ + 32) ^ kqi_w;
        wp2 = W + (long)(n0 + n_ + 64) * 1024 + koff + kqi_w * 4;  wn2 = (n_ + 64) ^ kqi_w;
        wp3 = W + (long)(n0 + n_ + 96) * 1024 + koff + kqi_w * 4;  wn3 = (n_ + 96) ^ kqi_w;
    }

    int xrow = tid >> 3;
    int xkq = (tid & 7) * 4;
    const float* xptr = X + xrow * (2 * DD) + koff + xkq;

    unsigned long long acc[4][4];
#pragma unroll
    for (int q = 0; q < 4; q++)
#pragma unroll
        for (int c = 0; c < 4; c++) acc[q][c] = 0ull;

    float4 xrg, wr0, wr1, wr2, wr3;

#define C_FETCH(k0_) do {                                                    \
        xrg = *(const float4*)(xptr + (k0_));                                \
        wr0 = *(const float4*)(wp0 + (k0_));                                 \
        wr1 = *(const float4*)(wp1 + (k0_));                                 \
        wr2 = *(const float4*)(wp2 + (k0_));                                 \
        wr3 = *(const float4*)(wp3 + (k0_));                                 \
    } while (0)

#define C_STORE(bi_) do {                                                    \
        *(float4*)&S.Xs[bi_][xrow][xkq] = xrg;                               \
        *(float4*)&S.Ws2[bi_][kqi_w][wn0][0] = wr0;                          \
        *(float4*)&S.Ws2[bi_][kqi_w][wn1][0] = wr1;                          \
        *(float4*)&S.Ws2[bi_][kqi_w][wn2][0] = wr2;                          \
        *(float4*)&S.Ws2[bi_][kqi_w][wn3][0] = wr3;                          \
    } while (0)

#define C_COMPUTE(bi_) do {                                                  \
        _Pragma("unroll")                                                    \
        for (int kqi = 0; kqi < 8; kqi++) {                                  \
            ulonglong2 xv0 = *(const ulonglong2*)&S.Xs[bi_][4 * w + 0][kqi * 4]; \
            ulonglong2 xv1 = *(const ulonglong2*)&S.Xs[bi_][4 * w + 1][kqi * 4]; \
            ulonglong2 xv2 = *(const ulonglong2*)&S.Xs[bi_][4 * w + 2][kqi * 4]; \
            ulonglong2 xv3 = *(const ulonglong2*)&S.Xs[bi_][4 * w + 3][kqi * 4]; \
            _Pragma("unroll")                                                \
            for (int c = 0; c < 4; c++) {                                    \
                ulonglong2 wv = *(const ulonglong2*)&S.Ws2[bi_][kqi][(tc + 32 * c) ^ kqi][0]; \
                FFMA2(acc[0][c], xv0.x, wv.x); FFMA2(acc[0][c], xv0.y, wv.y); \
                FFMA2(acc[1][c], xv1.x, wv.x); FFMA2(acc[1][c], xv1.y, wv.y); \
                FFMA2(acc[2][c], xv2.x, wv.x); FFMA2(acc[2][c], xv2.y, wv.y); \
                FFMA2(acc[3][c], xv3.x, wv.x); FFMA2(acc[3][c], xv3.y, wv.y); \
            }                                                                \
        }                                                                    \
    } while (0)

    C_FETCH(0);
    C_STORE(0);
    C_FETCH(32);
    __syncthreads();

    for (int t = 0; t < 8; t++) {
        if (t + 1 < 8) C_STORE((t + 1) & 1);
        if (t + 2 < 8) C_FETCH((t + 2) * 32);
        C_COMPUTE(t & 1);
        __syncthreads();
    }
#undef C_FETCH
#undef C_STORE
#undef C_COMPUTE

#pragma unroll
    for (int q = 0; q < 4; q++) {
        int b = 4 * w + q;
#pragma unroll
        for (int c = 0; c < 4; c++) {
            int n = n0 + tc + 32 * c;
            out[b * DD + n] = f2sum(acc[q][c]);
        }
    }
}

// ---------------------------------------------------------------------------
// Persistent wavefront kernel: all 47 diagonals in one launch.
// grid = NB blocks (all co-resident), software grid barrier between phases.
// ---------------------------------------------------------------------------
__global__ void __launch_bounds__(256, 1) wavefront_kernel(
    const float* __restrict__ W_hh, const float* __restrict__ W_ch,
    const float* __restrict__ W_cc, const float* __restrict__ b_ch,
    const float* __restrict__ b_cc)
{
    __shared__ TileSmem S;
    unsigned sense = 0;
    int bid = blockIdx.x;

    for (int d = 0; d <= PP + HHN - 2; d++) {
        int i_lo = d - (HHN - 1); if (i_lo < 0) i_lo = 0;
        int i_hi = d < (PP - 1) ? d : (PP - 1);
        int nc = i_hi - i_lo + 1;
        int njobs = nc * 32;

        for (int job = bid; job < njobs; job += NB) {
            int ci = job >> 5;
            gates_tile(S, W_hh, b_ch, b_cc, d, i_lo + ci, ci, (job & 31) * 32);
        }
        gsync(sense);

        for (int job = bid; job < njobs; job += NB) {
            int ci = job >> 5;
            cond_tile(S, W_ch, W_cc, i_lo + ci, ci, job & 31);
        }
        gsync(sense);
    }

    // Barrier state is back to {cnt=0, flag=0} (even barrier count); reset
    // explicitly as belt-and-braces for graph replays.
    if (bid == 0 && threadIdx.x == 0) { g_bar_cnt = 0; g_bar_flag = 0; }
}

// ---------------------------------------------------------------------------
// MLP layer: out = relu(X @ W.T + b), C[32 x 512], K = 512. grid = 4 blocks.
// Stage 0's X = final cell h = sum of 4 partials (slot 24) + b_ch.
// ---------------------------------------------------------------------------
__global__ void __launch_bounds__(256) mlp_kernel(
    const float* __restrict__ W, const float* __restrict__ bias,
    const float* __restrict__ bch, int stage)
{
    float* out = (stage == 0) ? &g_m1[0][0] : &g_m2[0][0];
    int n0 = blockIdx.x * 128;

    __shared__ float Xs[32][33];
    __shared__ float Ws[128][33];
    int tid = threadIdx.x;
    int tr = tid >> 5, tc = tid & 31;

    float acc[4][4];
#pragma unroll
    for (int a = 0; a < 4; a++)
#pragma unroll
        for (int b = 0; b < 4; b++) acc[a][b] = 0.f;

    for (int k0 = 0; k0 < DD; k0 += 32) {
        {
            int b = tid >> 3;
            int kq = (tid & 7) * 4;
            int k = k0 + kq;
            float4 v;
            if (stage == 0) {
                float4 p0 = *(const float4*)&g_ph[0][24][b][k];
                float4 p1 = *(const float4*)&g_ph[1][24][b][k];
                float4 p2 = *(const float4*)&g_ph[2][24][b][k];
                float4 p3 = *(const float4*)&g_ph[3][24][b][k];
                float4 bv = *(const float4*)(bch + k);
                v.x = bv.x + p0.x + p1.x + p2.x + p3.x;
                v.y = bv.y + p0.y + p1.y + p2.y + p3.y;
                v.z = bv.z + p0.z + p1.z + p2.z + p3.z;
                v.w = bv.w + p0.w + p1.w + p2.w + p3.w;
            } else {
                v = *(const float4*)(&g_m1[b][k]);
            }
            Xs[b][kq] = v.x; Xs[b][kq + 1] = v.y; Xs[b][kq + 2] = v.z; Xs[b][kq + 3] = v.w;
        }
#pragma unroll
        for (int t = 0; t < 4; t++) {
            int idx = tid + t * 256;
            int n = idx >> 3;
            int kq = (idx & 7) * 4;
            float4 w = *(const float4*)(W + (long)(n0 + n) * DD + k0 + kq);
            Ws[n][kq] = w.x; Ws[n][kq + 1] = w.y; Ws[n][kq + 2] = w.z; Ws[n][kq + 3] = w.w;
        }
        __syncthreads();
#pragma unroll
        for (int kk = 0; kk < 32; kk++) {
            float xv[4], wv[4];
#pragma unroll
            for (int rr = 0; rr < 4; rr++) xv[rr] = Xs[tr + 8 * rr][kk];
#pragma unroll
            for (int cc = 0; cc < 4; cc++) wv[cc] = Ws[cc * 32 + tc][kk];
#pragma unroll
            for (int rr = 0; rr < 4; rr++)
#pragma unroll
                for (int cc = 0; cc < 4; cc++)
                    acc[rr][cc] = fmaf(xv[rr], wv[cc], acc[rr][cc]);
        }
        __syncthreads();
    }

#pragma unroll
    for (int rr = 0; rr < 4; rr++) {
        int b = tr + 8 * rr;
#pragma unroll
        for (int cc = 0; cc < 4; cc++) {
            int n = n0 + cc * 32 + tc;
            out[b * DD + n] = fmaxf(acc[rr][cc] + bias[n], 0.f);
        }
    }
}

// ---------------------------------------------------------------------------
// Final: logits = g_m2 @ W3.T + b3 ; softmax over 3 classes. out [32,3] f32.
// ---------------------------------------------------------------------------
__global__ void __launch_bounds__(128) final_kernel(
    const float* __restrict__ W3, const float* __restrict__ b3, float* __restrict__ out)
{
    __shared__ float logits[32][3];
    int t = threadIdx.x;
    if (t < 96) {
        int b = t / 3, c = t % 3;
        float s = b3[c];
        for (int k = 0; k < DD; k++) s += g_m2[b][k] * W3[c * DD + k];
        logits[b][c] = s;
    }
    __syncthreads();
    if (t < 96) {
        int b = t / 3, c = t % 3;
        float mx = fmaxf(logits[b][0], fmaxf(logits[b][1], logits[b][2]));
        float e0 = expf(logits[b][0] - mx);
        float e1 = expf(logits[b][1] - mx);
        float e2 = expf(logits[b][2] - mx);
        out[b * 3 + c] = expf(logits[b][c] - mx) / (e0 + e1 + e2);
    }
}

// ---------------------------------------------------------------------------
extern "C" void kernel_launch(void* const* d_in, const int* in_sizes, int n_in,
                              void* d_out, int out_size)
{
    const int*   premise    = (const int*)d_in[0];
    const int*   hypothesis = (const int*)d_in[1];
    const float* emb        = (const float*)d_in[2];
    const float* W_ih       = (const float*)d_in[3];
    const float* W_hh       = (const float*)d_in[4];
    const float* b_ih       = (const float*)d_in[5];
    const float* b_hh       = (const float*)d_in[6];
    const float* W_ch       = (const float*)d_in[7];
    const float* b_ch       = (const float*)d_in[8];
    const float* W_cc       = (const float*)d_in[9];
    const float* b_cc       = (const float*)d_in[10];
    const float* W1         = (const float*)d_in[11];
    const float* b1         = (const float*)d_in[12];
    const float* W2         = (const float*)d_in[13];
    const float* b2         = (const float*)d_in[14];
    const float* W3         = (const float*)d_in[15];
    const float* b3         = (const float*)d_in[16];
    float* out = (float*)d_out;

    prologue_kernel<<<dim3(24, 32, 2), 256>>>(premise, hypothesis, emb, W_ih, b_ih, b_hh);
    wavefront_kernel<<<NB, 256>>>(W_hh, W_ch, W_cc, b_ch, b_cc);
    mlp_kernel<<<4, 256>>>(W1, b1, b_ch, 0);
    mlp_kernel<<<4, 256>>>(W2, b2, b_ch, 1);
    final_kernel<<<1, 128>>>(W3, b3, out);
}

// round 15
// speedup vs baseline: 1.0820x; 1.0820x over previous
#include <cuda_runtime.h>
#include <math.h>

#define BB  32
#define PP  24
#define HHN 24
#define EE  300
#define DD  512
#define GG  4096   // 8*D
#define DR  25     // slot 0 = zero boundary, slots 1..24 = grid rows 0..23
#define NB  296    // persistent blocks: 2 per SM (guaranteed by __launch_bounds__(256,2))

// Split-K condense partials: g_ph[ks][slot][b][n] = partial (no bias) of
// h-state over k-range [ks*256,(ks+1)*256). Slot = absolute row i + 1.
// Slot 0 never written -> stays zero -> zero boundary. Consumers sum 4
// partials + bias.
__device__ float g_ph[4][DR][BB][DD];
__device__ float g_pc[4][DR][BB][DD];
__device__ float g_zb[DD];              // zero bias page (never written)
// Hoisted input projections
__device__ float g_A[PP][BB][GG];
__device__ float g_Bh[HHN][BB][GG];
// Per-diagonal LSTM cell outputs (pre-condense), indexed by cell-on-diagonal.
__device__ float g_h2[HHN][BB][2*DD];
__device__ float g_c2[HHN][BB][2*DD];
// MLP intermediates
__device__ float g_m1[BB][DD];
__device__ float g_m2[BB][DD];

// Grid barrier state (returns to {0,0} after every launch: 94 = even syncs
// -> sense ends at 0; counter wraps to 0 at each barrier; plus explicit reset).
__device__ unsigned g_bar_cnt;
__device__ volatile unsigned g_bar_flag;

__device__ __forceinline__ float sigf(float x) { return 1.0f / (1.0f + expf(-x)); }

// Packed dual-FMA (sm_100+): d.lo += a.lo*b.lo ; d.hi += a.hi*b.hi
#define FFMA2(d, a, b) asm("fma.rn.f32x2 %0, %1, %2, %0;" : "+l"(d) : "l"(a), "l"(b))

__device__ __forceinline__ float f2sum(unsigned long long v) {
    return __uint_as_float((unsigned)v) + __uint_as_float((unsigned)(v >> 32));
}

// Sense-reversing centralized grid barrier. All NB blocks co-resident.
__device__ __forceinline__ void gsync(unsigned &sense) {
    __syncthreads();
    if (threadIdx.x == 0) {
        sense ^= 1u;
        __threadfence();
        unsigned old = atomicInc(&g_bar_cnt, NB - 1);
        if (old == NB - 1) {
            g_bar_flag = sense;
        } else {
            while (g_bar_flag != sense) __nanosleep(64);
        }
        __threadfence();
    }
    __syncthreads();
}

// ---------------------------------------------------------------------------
// Prologue: gather embeddings + input GEMMs into g_A / g_Bh.
// grid = (24 seq, 32 n-chunks of 128, 2 [A|Bh]), block = 256
// ---------------------------------------------------------------------------
__global__ void __launch_bounds__(256) prologue_kernel(
    const int* __restrict__ premise, const int* __restrict__ hypothesis,
    const float* __restrict__ emb, const float* __restrict__ W_ih,
    const float* __restrict__ b_ih, const float* __restrict__ b_hh)
{
    int seq = blockIdx.x;
    int n0  = blockIdx.y * 128;
    bool isA = (blockIdx.z == 0);
    const int* sidx = isA ? premise : hypothesis;   // both [B,24] row-major
    int coff = isA ? 0 : EE;

    __shared__ float Xs[32][33];
    __shared__ float Ws[128][33];
    __shared__ int   rows[32];

    int tid = threadIdx.x;
    int tr = tid >> 5, tc = tid & 31;
    if (tid < 32) rows[tid] = sidx[tid * 24 + seq];
    __syncthreads();

    float acc[4][4];
#pragma unroll
    for (int a = 0; a < 4; a++)
#pragma unroll
        for (int b = 0; b < 4; b++) acc[a][b] = 0.f;

    for (int k0 = 0; k0 < 320; k0 += 32) {
        {
            int b = tid >> 3;
            int kq = (tid & 7) * 4;
            int k = k0 + kq;
            float4 v = make_float4(0.f, 0.f, 0.f, 0.f);
            if (k < EE) v = *(const float4*)(emb + (long)rows[b] * EE + k);
            Xs[b][kq] = v.x; Xs[b][kq + 1] = v.y; Xs[b][kq + 2] = v.z; Xs[b][kq + 3] = v.w;
        }
#pragma unroll
        for (int t = 0; t < 4; t++) {
            int idx = tid + t * 256;
            int n = idx >> 3;
            int kq = (idx & 7) * 4;
            int k = k0 + kq;
            float4 w = make_float4(0.f, 0.f, 0.f, 0.f);
            if (k < EE) w = *(const float4*)(W_ih + (long)(n0 + n) * (2 * EE) + coff + k);
            Ws[n][kq] = w.x; Ws[n][kq + 1] = w.y; Ws[n][kq + 2] = w.z; Ws[n][kq + 3] = w.w;
        }
        __syncthreads();
#pragma unroll
        for (int kk = 0; kk < 32; kk++) {
            float xv[4], wv[4];
#pragma unroll
            for (int rr = 0; rr < 4; rr++) xv[rr] = Xs[tr + 8 * rr][kk];
#pragma unroll
            for (int cc = 0; cc < 4; cc++) wv[cc] = Ws[cc * 32 + tc][kk];
#pragma unroll
            for (int rr = 0; rr < 4; rr++)
#pragma unroll
                for (int cc = 0; cc < 4; cc++)
                    acc[rr][cc] = fmaf(xv[rr], wv[cc], acc[rr][cc]);
        }
        __syncthreads();
    }

    float* dst = isA ? &g_A[seq][0][0] : &g_Bh[seq][0][0];
#pragma unroll
    for (int rr = 0; rr < 4; rr++) {
        int b = tr + 8 * rr;
#pragma unroll
        for (int cc = 0; cc < 4; cc++) {
            int n = n0 + cc * 32 + tc;
            float v = acc[rr][cc];
            if (isA) v += b_ih[n] + b_hh[n];
            dst[b * GG + n] = v;
        }
    }
}

// ---------------------------------------------------------------------------
// Shared-memory tile storage used by both wavefront phases.
// ---------------------------------------------------------------------------
struct TileSmem {
    float Xs[2][32][32];          // [buf][b][kk]
    float Ws2[2][8][128][4];      // [buf][kqi][n^kqi][4]
};

// ---------------------------------------------------------------------------
// Gates tile: recurrent GEMM + fused LSTM nonlinearity for one (cell, m-chunk).
// C[32 x 128], K = 1024. X reconstructed as sum of 4 split-K partials + bias.
// ---------------------------------------------------------------------------
__device__ __forceinline__ void gates_tile(
    TileSmem& S, const float* __restrict__ W_hh,
    const float* __restrict__ b_ch, const float* __restrict__ b_cc,
    int d, int i, int ci, int m0)
{
    int j = d - i;

    int lsl = i;                              // left  (i-1, j): slot i
    int msl = (j == 0) ? 0 : (i + 1);         // lower (i, j-1): slot i+1
    const float* hbL = (i == 0) ? g_zb : b_ch;
    const float* hbM = (j == 0) ? g_zb : b_ch;
    const float* cbL = (i == 0) ? g_zb : b_cc;
    const float* cbM = (j == 0) ? g_zb : b_cc;

    int tid = threadIdx.x;
    int w = tid >> 5, tc = tid & 31;

    int kqi_w = tid & 7;
    const float* wp0, *wp1, *wp2, *wp3;
    int wn0, wn1, wn2, wn3;
    {
        int n0_ = (tid >> 3);
#define WROW(nn) (W_hh + (long)(((nn) >> 5) * 1024 + m0 + ((nn) & 31)) * 1024 + kqi_w * 4)
        wp0 = WROW(n0_);       wn0 = n0_ ^ kqi_w;
        wp1 = WROW(n0_ + 32);  wn1 = (n0_ + 32) ^ kqi_w;
        wp2 = WROW(n0_ + 64);  wn2 = (n0_ + 64) ^ kqi_w;
        wp3 = WROW(n0_ + 96);  wn3 = (n0_ + 96) ^ kqi_w;
#undef WROW
    }

    int xrow = tid >> 3;
    int xkq = (tid & 7) * 4;
    const float* lp0 = &g_ph[0][lsl][xrow][xkq];
    const float* lp1 = &g_ph[1][lsl][xrow][xkq];
    const float* lp2 = &g_ph[2][lsl][xrow][xkq];
    const float* lp3 = &g_ph[3][lsl][xrow][xkq];
    const float* mp0 = &g_ph[0][msl][xrow][xkq];
    const float* mp1 = &g_ph[1][msl][xrow][xkq];
    const float* mp2 = &g_ph[2][msl][xrow][xkq];
    const float* mp3 = &g_ph[3][msl][xrow][xkq];

    unsigned long long acc[4][4];
#pragma unroll
    for (int q = 0; q < 4; q++)
#pragma unroll
        for (int c = 0; c < 4; c++) acc[q][c] = 0ull;

    float4 xp0, xp1, xp2, xp3, xbv;
    float4 wr0, wr1, wr2, wr3;

#define G_FETCH(k0_) do {                                                    \
        if ((k0_) < 512) {                                                   \
            xp0 = *(const float4*)(lp0 + (k0_));                             \
            xp1 = *(const float4*)(lp1 + (k0_));                             \
            xp2 = *(const float4*)(lp2 + (k0_));                             \
            xp3 = *(const float4*)(lp3 + (k0_));                             \
            xbv = *(const float4*)(hbL + xkq + (k0_));                       \
        } else {                                                             \
            int kr_ = (k0_) - 512;                                           \
            xp0 = *(const float4*)(mp0 + kr_);                               \
            xp1 = *(const float4*)(mp1 + kr_);                               \
            xp2 = *(const float4*)(mp2 + kr_);                               \
            xp3 = *(const float4*)(mp3 + kr_);                               \
            xbv = *(const float4*)(hbM + xkq + kr_);                         \
        }                                                                    \
        wr0 = *(const float4*)(wp0 + (k0_));                                 \
        wr1 = *(const float4*)(wp1 + (k0_));                                 \
        wr2 = *(const float4*)(wp2 + (k0_));                                 \
        wr3 = *(const float4*)(wp3 + (k0_));                                 \
    } while (0)

#define G_STORE(bi_) do {                                                    \
        float4 xs_;                                                          \
        xs_.x = xbv.x + xp0.x + xp1.x + xp2.x + xp3.x;                       \
        xs_.y = xbv.y + xp0.y + xp1.y + xp2.y + xp3.y;                       \
        xs_.z = xbv.z + xp0.z + xp1.z + xp2.z + xp3.z;                       \
        xs_.w = xbv.w + xp0.w + xp1.w + xp2.w + xp3.w;                       \
        *(float4*)&S.Xs[bi_][xrow][xkq] = xs_;                               \
        *(float4*)&S.Ws2[bi_][kqi_w][wn0][0] = wr0;                          \
        *(float4*)&S.Ws2[bi_][kqi_w][wn1][0] = wr1;                          \
        *(float4*)&S.Ws2[bi_][kqi_w][wn2][0] = wr2;                          \
        *(float4*)&S.Ws2[bi_][kqi_w][wn3][0] = wr3;                          \
    } while (0)

#define G_COMPUTE(bi_) do {                                                  \
        _Pragma("unroll")                                                    \
        for (int kqi = 0; kqi < 8; kqi++) {                                  \
            ulonglong2 xv0 = *(const ulonglong2*)&S.Xs[bi_][4 * w + 0][kqi * 4]; \
            ulonglong2 xv1 = *(const ulonglong2*)&S.Xs[bi_][4 * w + 1][kqi * 4]; \
            ulonglong2 xv2 = *(const ulonglong2*)&S.Xs[bi_][4 * w + 2][kqi * 4]; \
            ulonglong2 xv3 = *(const ulonglong2*)&S.Xs[bi_][4 * w + 3][kqi * 4]; \
            _Pragma("unroll")                                                \
            for (int c = 0; c < 4; c++) {                                    \
                ulonglong2 wv = *(const ulonglong2*)&S.Ws2[bi_][kqi][(tc + 32 * c) ^ kqi][0]; \
                FFMA2(acc[0][c], xv0.x, wv.x); FFMA2(acc[0][c], xv0.y, wv.y); \
                FFMA2(acc[1][c], xv1.x, wv.x); FFMA2(acc[1][c], xv1.y, wv.y); \
                FFMA2(acc[2][c], xv2.x, wv.x); FFMA2(acc[2][c], xv2.y, wv.y); \
                FFMA2(acc[3][c], xv3.x, wv.x); FFMA2(acc[3][c], xv3.y, wv.y); \
            }                                                                \
        }                                                                    \
    } while (0)

    G_FETCH(0);
    G_STORE(0);
    G_FETCH(32);
    __syncthreads();

    for (int t = 0; t < 32; t++) {
        if (t + 1 < 32) G_STORE((t + 1) & 1);
        if (t + 2 < 32) G_FETCH((t + 2) * 32);
        G_COMPUTE(t & 1);
        __syncthreads();
    }
#undef G_FETCH
#undef G_STORE
#undef G_COMPUTE

    int m = m0 + tc;
    const float* Ai = &g_A[i][0][0];
    const float* Bj = &g_Bh[j][0][0];
    float* h2o = &g_h2[ci][0][0];
    float* c2o = &g_c2[ci][0][0];

    const float *cq0, *cq1, *cq2, *cq3;
    float cbv;
    if (m < DD) {
        cq0 = &g_pc[0][lsl][0][m]; cq1 = &g_pc[1][lsl][0][m];
        cq2 = &g_pc[2][lsl][0][m]; cq3 = &g_pc[3][lsl][0][m];
        cbv = cbL[m];
    } else {
        int mr = m - DD;
        cq0 = &g_pc[0][msl][0][mr]; cq1 = &g_pc[1][msl][0][mr];
        cq2 = &g_pc[2][msl][0][mr]; cq3 = &g_pc[3][msl][0][mr];
        cbv = cbM[mr];
    }

#pragma unroll
    for (int q = 0; q < 4; q++) {
        int b = 4 * w + q;
        long ab = (long)b * GG + m;
        float gi = f2sum(acc[q][0]) + Ai[ab]        + Bj[ab];
        float gf = f2sum(acc[q][1]) + Ai[ab + 1024] + Bj[ab + 1024];
        float gg = f2sum(acc[q][2]) + Ai[ab + 2048] + Bj[ab + 2048];
        float go = f2sum(acc[q][3]) + Ai[ab + 3072] + Bj[ab + 3072];
        float cp = cbv + cq0[b * DD] + cq1[b * DD] + cq2[b * DD] + cq3[b * DD];
        float c2 = sigf(gf) * cp + sigf(gi) * tanhf(gg);
        float h2 = sigf(go) * tanhf(c2);
        c2o[b * (2 * DD) + m] = c2;
        h2o[b * (2 * DD) + m] = h2;
    }
}

// ---------------------------------------------------------------------------
// Condense tile, split-K(4): one (cell, which/chunk/ksplit) job.
// C[32 x 128], K = 256 (8 tiles). Writes bias-free partials g_ph/g_pc[ks][i+1].
// ---------------------------------------------------------------------------
__device__ __forceinline__ void cond_tile(
    TileSmem& S, const float* __restrict__ W_ch, const float* __restrict__ W_cc,
    int i, int ci, int yy)
{
    int which = yy >> 4;                    // 0 -> h path, 1 -> c path
    int n0 = ((yy >> 2) & 3) * 128;
    int ks = yy & 3;
    int koff = ks * 256;

    const float* X = which ? &g_c2[ci][0][0] : &g_h2[ci][0][0];
    const float* W = which ? W_cc : W_ch;
    float* out = which ? &g_pc[ks][i + 1][0][0] : &g_ph[ks][i + 1][0][0];

    int tid = threadIdx.x;
    int w = tid >> 5, tc = tid & 31;

    int kqi_w = tid & 7;
    const float* wp0, *wp1, *wp2, *wp3;
    int wn0, wn1, wn2, wn3;
    {
        int n_ = (tid >> 3);
        wp0 = W + (long)(n0 + n_) * 1024 + koff + kqi_w * 4;       wn0 = n_ ^ kqi_w;
        wp1 = W + (long)(n0 + n_ + 32) * 1024 + koff + kqi_w * 4;  wn1 = (n_ + 32) ^ kqi_w;
        wp2 = W + (long)(n0 + n_ + 64) * 1024 + koff + kqi_w * 4;  wn2 = (n_ + 64) ^ kqi_w;
        wp3 = W + (long)(n0 + n_ + 96) * 1024 + koff + kqi_w * 4;  wn3 = (n_ + 96) ^ kqi_w;
    }

    int xrow = tid >> 3;
    int xkq = (tid & 7) * 4;
    const float* xptr = X + xrow * (2 * DD) + koff + xkq;

    unsigned long long acc[4][4];
#pragma unroll
    for (int q = 0; q < 4; q++)
#pragma unroll
        for (int c = 0; c < 4; c++) acc[q][c] = 0ull;

    float4 xrg, wr0, wr1, wr2, wr3;

#define C_FETCH(k0_) do {                                                    \
        xrg = *(const float4*)(xptr + (k0_));                                \
        wr0 = *(const float4*)(wp0 + (k0_));                                 \
        wr1 = *(const float4*)(wp1 + (k0_));                                 \
        wr2 = *(const float4*)(wp2 + (k0_));                                 \
        wr3 = *(const float4*)(wp3 + (k0_));                                 \
    } while (0)

#define C_STORE(bi_) do {                                                    \
        *(float4*)&S.Xs[bi_][xrow][xkq] = xrg;                               \
        *(float4*)&S.Ws2[bi_][kqi_w][wn0][0] = wr0;                          \
        *(float4*)&S.Ws2[bi_][kqi_w][wn1][0] = wr1;                          \
        *(float4*)&S.Ws2[bi_][kqi_w][wn2][0] = wr2;                          \
        *(float4*)&S.Ws2[bi_][kqi_w][wn3][0] = wr3;                          \
    } while (0)

#define C_COMPUTE(bi_) do {                                                  \
        _Pragma("unroll")                                                    \
        for (int kqi = 0; kqi < 8; kqi++) {                                  \
            ulonglong2 xv0 = *(const ulonglong2*)&S.Xs[bi_][4 * w + 0][kqi * 4]; \
            ulonglong2 xv1 = *(const ulonglong2*)&S.Xs[bi_][4 * w + 1][kqi * 4]; \
            ulonglong2 xv2 = *(const ulonglong2*)&S.Xs[bi_][4 * w + 2][kqi * 4]; \
            ulonglong2 xv3 = *(const ulonglong2*)&S.Xs[bi_][4 * w + 3][kqi * 4]; \
            _Pragma("unroll")                                                \
            for (int c = 0; c < 4; c++) {                                    \
                ulonglong2 wv = *(const ulonglong2*)&S.Ws2[bi_][kqi][(tc + 32 * c) ^ kqi][0]; \
                FFMA2(acc[0][c], xv0.x, wv.x); FFMA2(acc[0][c], xv0.y, wv.y); \
                FFMA2(acc[1][c], xv1.x, wv.x); FFMA2(acc[1][c], xv1.y, wv.y); \
                FFMA2(acc[2][c], xv2.x, wv.x); FFMA2(acc[2][c], xv2.y, wv.y); \
                FFMA2(acc[3][c], xv3.x, wv.x); FFMA2(acc[3][c], xv3.y, wv.y); \
            }                                                                \
        }                                                                    \
    } while (0)

    C_FETCH(0);
    C_STORE(0);
    C_FETCH(32);
    __syncthreads();

    for (int t = 0; t < 8; t++) {
        if (t + 1 < 8) C_STORE((t + 1) & 1);
        if (t + 2 < 8) C_FETCH((t + 2) * 32);
        C_COMPUTE(t & 1);
        __syncthreads();
    }
#undef C_FETCH
#undef C_STORE
#undef C_COMPUTE

#pragma unroll
    for (int q = 0; q < 4; q++) {
        int b = 4 * w + q;
#pragma unroll
        for (int c = 0; c < 4; c++) {
            int n = n0 + tc + 32 * c;
            out[b * DD + n] = f2sum(acc[q][c]);
        }
    }
}

// ---------------------------------------------------------------------------
// Persistent wavefront kernel: all 47 diagonals in one launch.
// grid = NB blocks, 2 per SM (guaranteed by launch bounds -> no deadlock),
// software grid barrier between phases.
// ---------------------------------------------------------------------------
__global__ void __launch_bounds__(256, 2) wavefront_kernel(
    const float* __restrict__ W_hh, const float* __restrict__ W_ch,
    const float* __restrict__ W_cc, const float* __restrict__ b_ch,
    const float* __restrict__ b_cc)
{
    __shared__ TileSmem S;
    unsigned sense = 0;
    int bid = blockIdx.x;

    for (int d = 0; d <= PP + HHN - 2; d++) {
        int i_lo = d - (HHN - 1); if (i_lo < 0) i_lo = 0;
        int i_hi = d < (PP - 1) ? d : (PP - 1);
        int nc = i_hi - i_lo + 1;
        int njobs = nc * 32;

        for (int job = bid; job < njobs; job += NB) {
            int ci = job >> 5;
            gates_tile(S, W_hh, b_ch, b_cc, d, i_lo + ci, ci, (job & 31) * 32);
        }
        gsync(sense);

        for (int job = bid; job < njobs; job += NB) {
            int ci = job >> 5;
            cond_tile(S, W_ch, W_cc, i_lo + ci, ci, job & 31);
        }
        gsync(sense);
    }

    // Barrier state is back to {cnt=0, flag=0} (even barrier count); reset
    // explicitly as belt-and-braces for graph replays.
    if (bid == 0 && threadIdx.x == 0) { g_bar_cnt = 0; g_bar_flag = 0; }
}

// ---------------------------------------------------------------------------
// MLP layer: out = relu(X @ W.T + b), C[32 x 512], K = 512. grid = 4 blocks.
// Stage 0's X = final cell h = sum of 4 partials (slot 24) + b_ch.
// ---------------------------------------------------------------------------
__global__ void __launch_bounds__(256) mlp_kernel(
    const float* __restrict__ W, const float* __restrict__ bias,
    const float* __restrict__ bch, int stage)
{
    float* out = (stage == 0) ? &g_m1[0][0] : &g_m2[0][0];
    int n0 = blockIdx.x * 128;

    __shared__ float Xs[32][33];
    __shared__ float Ws[128][33];
    int tid = threadIdx.x;
    int tr = tid >> 5, tc = tid & 31;

    float acc[4][4];
#pragma unroll
    for (int a = 0; a < 4; a++)
#pragma unroll
        for (int b = 0; b < 4; b++) acc[a][b] = 0.f;

    for (int k0 = 0; k0 < DD; k0 += 32) {
        {
            int b = tid >> 3;
            int kq = (tid & 7) * 4;
            int k = k0 + kq;
            float4 v;
            if (stage == 0) {
                float4 p0 = *(const float4*)&g_ph[0][24][b][k];
                float4 p1 = *(const float4*)&g_ph[1][24][b][k];
                float4 p2 = *(const float4*)&g_ph[2][24][b][k];
                float4 p3 = *(const float4*)&g_ph[3][24][b][k];
                float4 bv = *(const float4*)(bch + k);
                v.x = bv.x + p0.x + p1.x + p2.x + p3.x;
                v.y = bv.y + p0.y + p1.y + p2.y + p3.y;
                v.z = bv.z + p0.z + p1.z + p2.z + p3.z;
                v.w = bv.w + p0.w + p1.w + p2.w + p3.w;
            } else {
                v = *(const float4*)(&g_m1[b][k]);
            }
            Xs[b][kq] = v.x; Xs[b][kq + 1] = v.y; Xs[b][kq + 2] = v.z; Xs[b][kq + 3] = v.w;
        }
#pragma unroll
        for (int t = 0; t < 4; t++) {
            int idx = tid + t * 256;
            int n = idx >> 3;
            int kq = (idx & 7) * 4;
            float4 w = *(const float4*)(W + (long)(n0 + n) * DD + k0 + kq);
            Ws[n][kq] = w.x; Ws[n][kq + 1] = w.y; Ws[n][kq + 2] = w.z; Ws[n][kq + 3] = w.w;
        }
        __syncthreads();
#pragma unroll
        for (int kk = 0; kk < 32; kk++) {
            float xv[4], wv[4];
#pragma unroll
            for (int rr = 0; rr < 4; rr++) xv[rr] = Xs[tr + 8 * rr][kk];
#pragma unroll
            for (int cc = 0; cc < 4; cc++) wv[cc] = Ws[cc * 32 + tc][kk];
#pragma unroll
            for (int rr = 0; rr < 4; rr++)
#pragma unroll
                for (int cc = 0; cc < 4; cc++)
                    acc[rr][cc] = fmaf(xv[rr], wv[cc], acc[rr][cc]);
        }
        __syncthreads();
    }

#pragma unroll
    for (int rr = 0; rr < 4; rr++) {
        int b = tr + 8 * rr;
#pragma unroll
        for (int cc = 0; cc < 4; cc++) {
            int n = n0 + cc * 32 + tc;
            out[b * DD + n] = fmaxf(acc[rr][cc] + bias[n], 0.f);
        }
    }
}

// ---------------------------------------------------------------------------
// Final: logits = g_m2 @ W3.T + b3 ; softmax over 3 classes. out [32,3] f32.
// ---------------------------------------------------------------------------
__global__ void __launch_bounds__(128) final_kernel(
    const float* __restrict__ W3, const float* __restrict__ b3, float* __restrict__ out)
{
    __shared__ float logits[32][3];
    int t = threadIdx.x;
    if (t < 96) {
        int b = t / 3, c = t % 3;
        float s = b3[c];
        for (int k = 0; k < DD; k++) s += g_m2[b][k] * W3[c * DD + k];
        logits[b][c] = s;
    }
    __syncthreads();
    if (t < 96) {
        int b = t / 3, c = t % 3;
        float mx = fmaxf(logits[b][0], fmaxf(logits[b][1], logits[b][2]));
        float e0 = expf(logits[b][0] - mx);
        float e1 = expf(logits[b][1] - mx);
        float e2 = expf(logits[b][2] - mx);
        out[b * 3 + c] = expf(logits[b][c] - mx) / (e0 + e1 + e2);
    }
}

// ---------------------------------------------------------------------------
extern "C" void kernel_launch(void* const* d_in, const int* in_sizes, int n_in,
                              void* d_out, int out_size)
{
    const int*   premise    = (const int*)d_in[0];
    const int*   hypothesis = (const int*)d_in[1];
    const float* emb        = (const float*)d_in[2];
    const float* W_ih       = (const float*)d_in[3];
    const float* W_hh       = (const float*)d_in[4];
    const float* b_ih       = (const float*)d_in[5];
    const float* b_hh       = (const float*)d_in[6];
    const float* W_ch       = (const float*)d_in[7];
    const float* b_ch       = (const float*)d_in[8];
    const float* W_cc       = (const float*)d_in[9];
    const float* b_cc       = (const float*)d_in[10];
    const float* W1         = (const float*)d_in[11];
    const float* b1         = (const float*)d_in[12];
    const float* W2         = (const float*)d_in[13];
    const float* b2         = (const float*)d_in[14];
    const float* W3         = (const float*)d_in[15];
    const float* b3         = (const float*)d_in[16];
    float* out = (float*)d_out;

    prologue_kernel<<<dim3(24, 32, 2), 256>>>(premise, hypothesis, emb, W_ih, b_ih, b_hh);
    wavefront_kernel<<<NB, 256>>>(W_hh, W_ch, W_cc, b_ch, b_cc);
    mlp_kernel<<<4, 256>>>(W1, b1, b_ch, 0);
    mlp_kernel<<<4, 256>>>(W2, b2, b_ch, 1);
    final_kernel<<<1, 128>>>(W3, b3, out);
}